// round 11
// baseline (speedup 1.0000x reference)
#include <cuda_runtime.h>
#include <cuda_fp16.h>
#include <cstdint>

// Problem constants
#define B_    128
#define A_    30
#define T_    65
#define FIN_  4
#define H_    1920
#define G4_   7680
#define NSTEP 64

// GEMM tiling: CTA tile 128(M) x 64(N), K chunk = 64 fp16
#define KCHUNKS  30                 // 1920/64 per phase
#define NSTG     4                  // pipeline stages
#define STAGE_B  24576              // A 16K + W 8K
#define SMEMB    (1024 + 1024 + NSTG * STAGE_B)
#define LOFF     14745600u          // per-layer elems in tiled LSTM weights
#define NCTA     128
#define NTHR     256

// ---------------- device scratch (no allocation allowed) ----------------
__device__ __align__(1024) __half g_wih[2u*7680u*1920u];
__device__ __align__(1024) __half g_whh[2u*7680u*1920u];
__device__ __align__(1024) __half g_w3[1920u*1920u];
__device__ __align__(1024) __half g_x[245760];     // 30 chunks x 8192 (128 rows x 64 k)
__device__ __align__(1024) __half g_h0[245760];
__device__ __align__(1024) __half g_h1[245760];
__device__ float g_c[2 * B_ * H_];
__device__ float g_gates[B_ * G4_];
__device__ float g_r3[3 * B_ * H_];                // W3 split-K disjoint slices
__device__ unsigned g_bcnt;
__device__ unsigned g_bgen;

// ---------------- PTX helpers ----------------
__device__ __forceinline__ uint32_t smem_u32(const void* p) {
    uint32_t a;
    asm("{ .reg .u64 t; cvta.to.shared.u64 t, %1; cvt.u32.u64 %0, t; }" : "=r"(a) : "l"(p));
    return a;
}
#define MBAR_INIT(addr, cnt) \
    asm volatile("mbarrier.init.shared.b64 [%0], %1;" :: "r"(addr), "r"((uint32_t)(cnt)) : "memory")
#define MBAR_EXPECT_TX(addr, bytes) \
    asm volatile("mbarrier.arrive.expect_tx.shared.b64 _, [%0], %1;" :: "r"(addr), "r"((uint32_t)(bytes)) : "memory")
#define MBAR_ARRIVE(addr) \
    asm volatile("mbarrier.arrive.shared.b64 _, [%0];" :: "r"(addr) : "memory")
#define MBAR_WAIT(addr, par) do { \
    uint32_t _m=(addr), _p=(par), _d; \
    asm volatile("{\n\t.reg .pred p;\n\tmbarrier.try_wait.parity.acquire.cta.shared::cta.b64 p, [%1], %2;\n\tselp.b32 %0,1,0,p;\n\t}" \
        : "=r"(_d) : "r"(_m), "r"(_p) : "memory"); \
    if (!_d) { \
        asm volatile("{\n\t.reg .pred P1;\n\tWL_%=:\n\tmbarrier.try_wait.parity.acquire.cta.shared::cta.b64 P1, [%0], %1, 0x989680;\n\t@P1 bra.uni WD_%=;\n\tbra.uni WL_%=;\n\tWD_%=:\n\t}" \
            :: "r"(_m), "r"(_p) : "memory"); \
    } } while (0)
#define BULK_G2S(dst, src, bytes, mbar) \
    asm volatile("cp.async.bulk.shared::cluster.global.mbarrier::complete_tx::bytes [%0], [%1], %2, [%3];" \
        :: "r"(dst), "l"(src), "r"((uint32_t)(bytes)), "r"(mbar) : "memory")

#define LDSM4(r, addr) \
    asm volatile("ldmatrix.sync.aligned.m8n8.x4.shared.b16 {%0,%1,%2,%3}, [%4];" \
        : "=r"((r)[0]), "=r"((r)[1]), "=r"((r)[2]), "=r"((r)[3]) : "r"(addr))
#define MMA(d, a, b0v, b1v) \
    asm volatile("mma.sync.aligned.m16n8k16.row.col.f32.f16.f16.f32 " \
        "{%0,%1,%2,%3}, {%4,%5,%6,%7}, {%8,%9}, {%0,%1,%2,%3};" \
        : "+f"((d)[0]), "+f"((d)[1]), "+f"((d)[2]), "+f"((d)[3]) \
        : "r"((a)[0]), "r"((a)[1]), "r"((a)[2]), "r"((a)[3]), "r"(b0v), "r"(b1v))

__device__ __forceinline__ uint32_t sw128(uint32_t o) { return o ^ ((o >> 3) & 0x70); }
__device__ __forceinline__ uint32_t act_idx(int row, int k) {
    return (uint32_t)((k >> 6) * 8192) + (sw128((uint32_t)(row * 128 + (k & 63) * 2)) >> 1);
}

// ---------------- grid-wide sync (all 128 CTAs co-resident) ----------------
__device__ __forceinline__ void gsync() {
    __syncthreads();
    __threadfence();
    asm volatile("fence.proxy.async;" ::: "memory");
    __syncthreads();
    if (threadIdx.x == 0) {
        volatile unsigned* cnt = &g_bcnt;
        volatile unsigned* gen = &g_bgen;
        unsigned g = *gen;
        unsigned a = atomicAdd((unsigned*)&g_bcnt, 1u);
        if (a == NCTA - 1) { *cnt = 0; __threadfence(); *gen = g + 1; }
        else { while (*gen == g) __nanosleep(64); }
        __threadfence();
    }
    __syncthreads();
}

// ---------------- weight conversion: fp32 [N,1920] -> swizzled fp16 64x64 tiles ----------------
__global__ void __launch_bounds__(256) conv_w(
    const float* __restrict__ src, __half* __restrict__ dst, int total)
{
    int i = blockIdx.x * 256 + threadIdx.x;
    if (i >= total) return;
    int n = i / H_, k = i - n * H_;
    uint32_t d = (uint32_t)((n >> 6) * KCHUNKS + (k >> 6)) * 4096
               + (sw128((uint32_t)((n & 63) * 128 + (k & 63) * 2)) >> 1);
    dst[d] = __float2half(src[i]);
}

// ---------------- GEMM phase (device function, persistent pipeline state) ----------------
#define ISSUE_CHUNK(lc, stgA, mbarA) do { \
    int _p = (nph == 2 && (lc) >= KCHUNKS) ? 1 : 0; \
    int _k = (nph == 2) ? ((lc) - _p * KCHUNKS) : (cbeg + (lc)); \
    const __half* _A = (_p ? A1 : A0) + (size_t)_k * 8192; \
    const __half* _W = (_p ? W1 : W0) + ((size_t)nt * KCHUNKS + _k) * 4096; \
    MBAR_EXPECT_TX(mbarA, STAGE_B); \
    BULK_G2S((stgA),         _A, 16384, mbarA); \
    BULK_G2S((stgA) + 16384, _W,  8192, mbarA); \
} while (0)

__device__ void gemm_phase(
    float* C, int ldc, int sliceStride, int slice,
    const __half* A0, const __half* W0,
    const __half* A1, const __half* W1,
    const float* bias0, const float* bias1,
    int nph, int ccnt, int nt, unsigned gbase, uint32_t sb)
{
    const uint32_t FULL = sb;
    const uint32_t DONE = sb + 64;
    const uint32_t STG0 = sb + 1024;
    const int tid = threadIdx.x;
    const int wid = tid >> 5, lane = tid & 31;
    const int cbeg = slice * ccnt;
    const int NCH = (nph == 2) ? 2 * KCHUNKS : ccnt;
    const int wm = (wid & 3) * 32;
    const int wn = (wid >> 2) * 32;

    // prologue: issue first NSTG chunks (waiting prior-phase consumption of the stage)
    if (tid == 0) {
        for (int c = 0; c < NSTG && c < NCH; c++) {
            unsigned gc = gbase + c;
            if (gc >= NSTG) MBAR_WAIT(DONE + 8 * (gc & 3), ((gc - NSTG) >> 2) & 1);
            ISSUE_CHUNK(c, STG0 + (gc & 3) * STAGE_B, FULL + 8 * (gc & 3));
        }
    }

    float acc[2][4][4];
#pragma unroll
    for (int i = 0; i < 2; i++)
#pragma unroll
        for (int jn = 0; jn < 4; jn++)
#pragma unroll
            for (int q = 0; q < 4; q++) acc[i][jn][q] = 0.f;

    const int a_row  = (lane & 7) + ((lane >> 3) & 1) * 8;
    const int a_koff = (lane >> 4) * 16;
    const int w_row  = (lane & 7) + ((lane >> 4) << 3);
    const int w_koff = ((lane >> 3) & 1) * 16;

    for (int c = 0; c < NCH; c++) {
        unsigned gc = gbase + c;
        int s = gc & 3;
        MBAR_WAIT(FULL + 8 * s, (gc >> 2) & 1);
        uint32_t stg = STG0 + s * STAGE_B;

#pragma unroll
        for (int kb = 0; kb < 4; kb++) {
            uint32_t av[2][4], wv[2][4];
#pragma unroll
            for (int mt = 0; mt < 2; mt++) {
                uint32_t ad = stg + sw128((uint32_t)((wm + mt * 16 + a_row) * 128 + kb * 32 + a_koff));
                LDSM4(av[mt], ad);
            }
#pragma unroll
            for (int hf = 0; hf < 2; hf++) {
                uint32_t wd = stg + 16384 + sw128((uint32_t)((wn + hf * 16 + w_row) * 128 + kb * 32 + w_koff));
                LDSM4(wv[hf], wd);
            }
#pragma unroll
            for (int mt = 0; mt < 2; mt++) {
#pragma unroll
                for (int hf = 0; hf < 2; hf++) {
                    MMA(acc[mt][2 * hf],     av[mt], wv[hf][0], wv[hf][1]);
                    MMA(acc[mt][2 * hf + 1], av[mt], wv[hf][2], wv[hf][3]);
                }
            }
        }
        __syncwarp();
        if (lane == 0) MBAR_ARRIVE(DONE + 8 * s);

        if (tid == 0 && c + NSTG < NCH) {
            unsigned gn = gc + NSTG;
            MBAR_WAIT(DONE + 8 * (gn & 3), ((gn - NSTG) >> 2) & 1);
            ISSUE_CHUNK(c + NSTG, STG0 + (gn & 3) * STAGE_B, FULL + 8 * (gn & 3));
        }
    }

    float* Cb = C + (size_t)slice * sliceStride;
#pragma unroll
    for (int mt = 0; mt < 2; mt++) {
        int r0 = wm + mt * 16 + (lane >> 2);
        float* cp = Cb + (size_t)r0 * ldc;
#pragma unroll
        for (int ng = 0; ng < 4; ng++) {
            int col = nt * 64 + wn + ng * 8 + 2 * (lane & 3);
            float b0v = 0.f, b1v = 0.f;
            if (bias0) { b0v = bias0[col] + bias1[col]; b1v = bias0[col + 1] + bias1[col + 1]; }
            *(float2*)(cp + col) = make_float2(acc[mt][ng][0] + b0v, acc[mt][ng][1] + b1v);
            *(float2*)(cp + 8 * ldc + col) = make_float2(acc[mt][ng][2] + b0v, acc[mt][ng][3] + b1v);
        }
    }
}

// ---------------- LSTM cell phase (grid-strided) ----------------
__device__ void cell_phase(const float* gates, float* c, __half* h)
{
    int gtid = blockIdx.x * NTHR + threadIdx.x;
    for (int idx = gtid; idx < B_ * H_; idx += NCTA * NTHR) {
        int b = idx / H_;
        int jj = idx - b * H_;
        const float* g = gates + b * G4_;
        float ig = g[jj], fg = g[H_ + jj], gg = g[2 * H_ + jj], og = g[3 * H_ + jj];
        float si = 1.f / (1.f + expf(-ig));
        float sf = 1.f / (1.f + expf(-fg));
        float so = 1.f / (1.f + expf(-og));
        float tg = tanhf(gg);
        float cn = sf * c[idx] + si * tg;
        float hn = so * tanhf(cn);
        c[idx] = cn;
        h[act_idx(b, jj)] = __float2half(hn);
    }
}

// ---------------- tail phase: W3 slice-sum + bias/relu + W4 + residual + out, then MLP ----------------
__device__ void tail_phase(
    float* sm,
    const float* r3, const float* b3, const float* W4, const float* b4,
    const float* inputs, float* out, __half* x,
    const float* W1, const float* b1, const float* W2, const float* b2,
    int t, int produce, const int* burn, int do_w4)
{
    float* xs    = sm;           // 1920
    float* W2t   = sm + 1920;    // 4096
    float* W1t   = sm + 6016;    // 256
    float* b1s   = sm + 6272;    // 64
    float* b2s   = sm + 6336;    // 64
    float* ins_s = sm + 6400;    // 120
    float* x1s   = sm + 6520;    // 1920
    float* outs  = sm + 8440;    // 120

    const int b = blockIdx.x;
    const int tid = threadIdx.x;
    const int bi = burn ? *burn : 20;

    if (do_w4) {
        for (int k = tid; k < H_; k += NTHR)
            xs[k] = fmaxf(r3[b * H_ + k] + r3[(B_ + b) * H_ + k] + r3[(2 * B_ + b) * H_ + k] + b3[k], 0.f);
        __syncthreads();
        if (tid < A_ * FIN_) {
            const float4* wp = (const float4*)(W4 + tid * H_);
            const float4* xp = (const float4*)xs;
            float a0 = 0.f, a1 = 0.f, a2 = 0.f, a3 = 0.f;
#pragma unroll 4
            for (int k = 0; k < H_ / 4; k++) {
                float4 w = wp[k]; float4 xv = xp[k];
                a0 = fmaf(w.x, xv.x, a0); a1 = fmaf(w.y, xv.y, a1);
                a2 = fmaf(w.z, xv.z, a2); a3 = fmaf(w.w, xv.w, a3);
            }
            float acc = b4[tid] + (a0 + a1) + (a2 + a3);
            int a = tid >> 2, f = tid & 3;
            int r = b * A_ + a;
            float insv = (t <= bi) ? inputs[(r * T_ + t) * FIN_ + f]
                                   : out[(r * NSTEP + t - 1) * FIN_ + f];
            float ov = acc + insv;
            out[(r * NSTEP + t) * FIN_ + f] = ov;
            outs[tid] = ov;
        }
        __syncthreads();
    }

    if (produce >= NSTEP) return;   // uniform across grid

    for (int i = tid; i < 64 * 64; i += NTHR) {
        int jj = i >> 6, kk = i & 63;
        W2t[kk * 64 + jj] = W2[i];
    }
    for (int i = tid; i < 256; i += NTHR) {
        int jj = i >> 2, ff = i & 3;
        W1t[ff * 64 + jj] = W1[i];
    }
    if (tid < 64) { b1s[tid] = b1[tid]; b2s[tid] = b2[tid]; }
    if (tid < A_ * FIN_) {
        int a = tid >> 2, f = tid & 3;
        int r = b * A_ + a;
        ins_s[tid] = (produce <= bi) ? inputs[(r * T_ + produce) * FIN_ + f] : outs[tid];
    }
    __syncthreads();

    for (int idx = tid; idx < A_ * 64; idx += NTHR) {
        int a = idx >> 6, j = idx & 63;
        float v = b1s[j];
#pragma unroll
        for (int f = 0; f < 4; f++) v = fmaf(ins_s[a * 4 + f], W1t[f * 64 + j], v);
        x1s[idx] = fmaxf(v, 0.f);
    }
    __syncthreads();

    for (int idx = tid; idx < A_ * 64; idx += NTHR) {
        int a = idx >> 6, j = idx & 63;
        float v = b2s[j];
        const float* x1p = x1s + a * 64;
#pragma unroll
        for (int k = 0; k < 64; k++) v = fmaf(x1p[k], W2t[k * 64 + j], v);
        v = fmaxf(v, 0.f);
        x[act_idx(b, a * 64 + j)] = __float2half(v);
    }
}

// ---------------- persistent mega-kernel: all 64 steps ----------------
__global__ void __launch_bounds__(NTHR, 1) mega_kernel(
    const float* __restrict__ inputs,
    const float* __restrict__ W1, const float* __restrict__ b1,
    const float* __restrict__ W2, const float* __restrict__ b2,
    const float* __restrict__ bih, const float* __restrict__ bhh,
    const float* __restrict__ b3, const float* __restrict__ W4,
    const float* __restrict__ b4,
    float* __restrict__ out, const int* __restrict__ burn)
{
    extern __shared__ char smraw[];
    char* sm = (char*)(((unsigned long long)smraw + 1023ull) & ~1023ull);
    const uint32_t sb = smem_u32(sm);
    float* tailsm = (float*)(sm + 1024);

    if (threadIdx.x == 0) {
        for (int s = 0; s < NSTG; s++) { MBAR_INIT(sb + 8 * s, 1); MBAR_INIT(sb + 64 + 8 * s, 8); }
        asm volatile("fence.proxy.async.shared::cta;" ::: "memory");
    }
    __syncthreads();

    unsigned pipe_gc = 0;
    const int cta = blockIdx.x;
    float* c0 = g_c;
    float* c1 = g_c + B_ * H_;

    // initial MLP (produce x for t=0)
    tail_phase(tailsm, g_r3, b3, W4, b4, inputs, out, g_x, W1, b1, W2, b2, 0, 0, burn, 0);
    gsync();

    for (int t = 0; t < NSTEP; t++) {
        // layer 0: gates = x@Wih0^T + h0@Whh0^T + biases
        if (cta < 120) {
            gemm_phase(g_gates, G4_, 0, 0, g_x, g_wih, g_h0, g_whh,
                       bih, bhh, 2, 0, cta, pipe_gc, sb);
            pipe_gc += 2 * KCHUNKS;
        }
        gsync();
        cell_phase(g_gates, c0, g_h0);
        gsync();

        // layer 1: gates = h0@Wih1^T + h1@Whh1^T + biases
        if (cta < 120) {
            gemm_phase(g_gates, G4_, 0, 0, g_h0, g_wih + LOFF, g_h1, g_whh + LOFF,
                       bih + G4_, bhh + G4_, 2, 0, cta, pipe_gc, sb);
            pipe_gc += 2 * KCHUNKS;
        }
        gsync();
        cell_phase(g_gates, c1, g_h1);
        gsync();

        // W3: 90 CTAs, split-K=3 disjoint slices
        if (cta < 90) {
            gemm_phase(g_r3, H_, B_ * H_, cta / 30, g_h1, g_w3,
                       nullptr, nullptr, nullptr, nullptr, 1, 10, cta % 30, pipe_gc, sb);
            pipe_gc += 10;
        }
        gsync();

        // tail: W3-sum + bias/relu + W4 + residual + out, then MLP for t+1
        tail_phase(tailsm, g_r3, b3, W4, b4, inputs, out, g_x,
                   W1, b1, W2, b2, t, t + 1, burn, 1);
        gsync();
    }
}

// ---------------- launch ----------------
extern "C" void kernel_launch(void* const* d_in, const int* in_sizes, int n_in,
                              void* d_out, int out_size)
{
    const float* inputs = (const float*)d_in[0];
    const float* W1  = (const float*)d_in[1];
    const float* b1  = (const float*)d_in[2];
    const float* W2  = (const float*)d_in[3];
    const float* b2  = (const float*)d_in[4];
    const float* Wih = (const float*)d_in[5];
    const float* Whh = (const float*)d_in[6];
    const float* bih = (const float*)d_in[7];
    const float* bhh = (const float*)d_in[8];
    const float* W3  = (const float*)d_in[9];
    const float* b3  = (const float*)d_in[10];
    const float* W4  = (const float*)d_in[11];
    const float* b4  = (const float*)d_in[12];
    const int* burn  = (n_in > 14) ? (const int*)d_in[14] : nullptr;
    float* out = (float*)d_out;

    cudaFuncSetAttribute(mega_kernel, cudaFuncAttributeMaxDynamicSharedMemorySize, SMEMB);

    void *pwih, *pwhh, *pw3, *ph0, *ph1, *pc, *pbc, *pbg;
    cudaGetSymbolAddress(&pwih, g_wih);
    cudaGetSymbolAddress(&pwhh, g_whh);
    cudaGetSymbolAddress(&pw3, g_w3);
    cudaGetSymbolAddress(&ph0, g_h0);
    cudaGetSymbolAddress(&ph1, g_h1);
    cudaGetSymbolAddress(&pc, g_c);
    cudaGetSymbolAddress(&pbc, g_bcnt);
    cudaGetSymbolAddress(&pbg, g_bgen);

    // zero recurrent state + barrier state (every launch: graph replays must be deterministic)
    cudaMemsetAsync(pc, 0, sizeof(float) * 2 * B_ * H_);
    cudaMemsetAsync(ph0, 0, sizeof(__half) * 245760);
    cudaMemsetAsync(ph1, 0, sizeof(__half) * 245760);
    cudaMemsetAsync(pbc, 0, sizeof(unsigned));
    cudaMemsetAsync(pbg, 0, sizeof(unsigned));

    // convert weights to pre-swizzled fp16 tiles (once per launch)
    const int TOT_IH = 2 * G4_ * H_;
    const int TOT_W3 = H_ * H_;
    conv_w<<<(TOT_IH + 255) / 256, 256>>>(Wih, (__half*)pwih, TOT_IH);
    conv_w<<<(TOT_IH + 255) / 256, 256>>>(Whh, (__half*)pwhh, TOT_IH);
    conv_w<<<(TOT_W3 + 255) / 256, 256>>>(W3, (__half*)pw3, TOT_W3);

    // one persistent kernel for the whole 64-step rollout
    mega_kernel<<<NCTA, NTHR, SMEMB>>>(inputs, W1, b1, W2, b2, bih, bhh,
                                       b3, W4, b4, out, burn);
}